// round 1
// baseline (speedup 1.0000x reference)
#include <cuda_runtime.h>

#define M_V 50000   // vocab
#define N_F 1000    // filters
#define K_D 300     // embedding dim
#define B_B 128
#define L_L 512

// 200 MB scratch: vocab x filter score table
__device__ float g_S[(size_t)M_V * N_F];

// ---------------------------------------------------------------------------
// Phase 1: S[v,f] = sum_k emb[v,k] * conv_w[f,k]
// NT GEMM, M=50000, N=1000, K=300. Block tile 128x128, BK=4, 256 thr, 8x8 micro.
// Rows are 300 floats = 1200 B (16B aligned), K multiple of 4 -> clean float4.
// ---------------------------------------------------------------------------
__global__ __launch_bounds__(256, 2) void sgemm_nt(const float* __restrict__ A,
                                                   const float* __restrict__ Bm) {
    __shared__ float As[4][128];
    __shared__ float Bs[4][128];

    const int tid = threadIdx.x;
    const int bm = blockIdx.y * 128;
    const int bn = blockIdx.x * 128;
    const int tx = tid & 15;   // n direction (16 threads)
    const int ty = tid >> 4;   // m direction (16 threads)

    // load role: threads 0-127 load A rows, 128-255 load B rows
    const int  lr    = tid & 127;
    const bool isB   = tid >= 128;
    const int  grow  = (isB ? bn : bm) + lr;
    const bool rowok = grow < (isB ? N_F : M_V);
    const float* gsrc = (isB ? Bm : A) + (size_t)grow * K_D;
    float* sdst = (isB ? &Bs[0][0] : &As[0][0]) + lr;

    float acc[8][8];
#pragma unroll
    for (int i = 0; i < 8; i++)
#pragma unroll
        for (int j = 0; j < 8; j++) acc[i][j] = 0.f;

    float4 v = make_float4(0.f, 0.f, 0.f, 0.f);
    if (rowok) v = *(const float4*)(gsrc);

    for (int k0 = 0; k0 < K_D; k0 += 4) {
        __syncthreads();
        sdst[0]   = v.x;
        sdst[128] = v.y;
        sdst[256] = v.z;
        sdst[384] = v.w;
        __syncthreads();

        // prefetch next k-slice while computing this one
        if (k0 + 4 < K_D) {
            v = rowok ? *(const float4*)(gsrc + k0 + 4)
                      : make_float4(0.f, 0.f, 0.f, 0.f);
        }

#pragma unroll
        for (int kk = 0; kk < 4; kk++) {
            float ar[8], br[8];
#pragma unroll
            for (int i = 0; i < 8; i++) ar[i] = As[kk][ty * 8 + i];
#pragma unroll
            for (int j = 0; j < 8; j++) br[j] = Bs[kk][tx * 8 + j];
#pragma unroll
            for (int i = 0; i < 8; i++)
#pragma unroll
                for (int j = 0; j < 8; j++)
                    acc[i][j] = fmaf(ar[i], br[j], acc[i][j]);
        }
    }

#pragma unroll
    for (int i = 0; i < 8; i++) {
        int m = bm + ty * 8 + i;
        if (m < M_V) {
#pragma unroll
            for (int j = 0; j < 8; j += 4) {
                int n = bn + tx * 8 + j;
                if (n < N_F) {   // n mult of 4, N_F mult of 4 -> whole float4 valid
                    float4 o = make_float4(acc[i][j], acc[i][j + 1],
                                           acc[i][j + 2], acc[i][j + 3]);
                    *(float4*)(&g_S[(size_t)m * N_F + n]) = o;
                }
            }
        }
    }
}

// ---------------------------------------------------------------------------
// Phase 2: per (b,f): first-index argmax over t of S[inp[b,t],f];
// val = relu(max + conv_b[f]); contrib = val*(fc_w[1,f]-fc_w[0,f]);
// token[b,argmax] += contrib; token += fc_b[1]-fc_b[0].
// One block per b, 1024 threads (f = tid). Deterministic ordered reduction.
// ---------------------------------------------------------------------------
__global__ __launch_bounds__(1024) void reduce_scatter(
    const int* __restrict__ inp, const float* __restrict__ cb,
    const float* __restrict__ fcw, const float* __restrict__ fcb,
    float* __restrict__ out) {
    __shared__ int   sw[L_L];
    __shared__ int   sbt[N_F];
    __shared__ float sct[N_F];

    const int b = blockIdx.x;
    const int tid = threadIdx.x;

    if (tid < L_L) sw[tid] = inp[b * L_L + tid];
    __syncthreads();

    const int f = tid;
    if (f < N_F) {
        const float* Sf = g_S + f;
        float best = -3.4e38f;
        int bestt = 0;
        for (int t0 = 0; t0 < L_L; t0 += 8) {
            float vv[8];
#pragma unroll
            for (int j = 0; j < 8; j++)
                vv[j] = Sf[(size_t)sw[t0 + j] * N_F];
#pragma unroll
            for (int j = 0; j < 8; j++) {
                if (vv[j] > best) { best = vv[j]; bestt = t0 + j; }  // strict > => first index
            }
        }
        float val = fmaxf(best + cb[f], 0.f);          // relu(max) == max(relu)
        float contrib = val * (fcw[N_F + f] - fcw[f]); // zero when val==0 -> index moot
        sbt[f] = bestt;
        sct[f] = contrib;
    }
    __syncthreads();

    if (tid < L_L) {
        float accv = fcb[1] - fcb[0];
        // ordered, deterministic gather over filters
        for (int ff = 0; ff < N_F; ff++) {
            if (sbt[ff] == tid) accv += sct[ff];
        }
        out[b * L_L + tid] = accv;
    }
}

extern "C" void kernel_launch(void* const* d_in, const int* in_sizes, int n_in,
                              void* d_out, int out_size) {
    const int*   inp    = (const int*)d_in[0];
    const float* emb    = (const float*)d_in[1];
    const float* conv_w = (const float*)d_in[2];   // [1000,1,300] contiguous
    const float* conv_b = (const float*)d_in[3];
    const float* fc_w   = (const float*)d_in[4];   // [2,1000]
    const float* fc_b   = (const float*)d_in[5];
    float* out = (float*)d_out;

    dim3 g1((N_F + 127) / 128, (M_V + 127) / 128);  // 8 x 391
    sgemm_nt<<<g1, 256>>>(emb, conv_w);
    reduce_scatter<<<B_B, 1024>>>(inp, conv_b, fc_w, fc_b, out);
}

// round 3
// speedup vs baseline: 1.4817x; 1.4817x over previous
#include <cuda_runtime.h>
#include <cstdint>

#define M_V 50000   // vocab
#define N_F 1000    // filters
#define K_D 300     // embedding dim
#define B_B 128
#define L_L 512

// 200 MB scratch: vocab x filter score table S[v,f], row stride 1000
__device__ float g_S[(size_t)M_V * N_F];

#define BM 128
#define BN 128
#define BK 16
#define LDSS 20          // padded smem row stride (floats): conflict-free frags
#define NCHUNK 19        // ceil(300/16)

__device__ __forceinline__ uint32_t f2tf32(float x) {
    uint32_t u;
    asm("cvt.rna.tf32.f32 %0, %1;" : "=r"(u) : "f"(x));
    return u;
}

__device__ __forceinline__ void mma8(float* c, const uint32_t* a, const uint32_t* b) {
    asm volatile(
        "mma.sync.aligned.m16n8k8.row.col.f32.tf32.tf32.f32 "
        "{%0,%1,%2,%3}, {%4,%5,%6,%7}, {%8,%9}, {%0,%1,%2,%3};"
        : "+f"(c[0]), "+f"(c[1]), "+f"(c[2]), "+f"(c[3])
        : "r"(a[0]), "r"(a[1]), "r"(a[2]), "r"(a[3]), "r"(b[0]), "r"(b[1]));
}

// ===========================================================================
// Phase 1: S[v,f] = emb[v,:] . conv_w[f,:]  via 3xTF32 mma.sync GEMM (NT)
// CTA tile 128x128, BK=16, 8 warps (2x4), warptile 64x32, 3 passes hh/hl/lh.
// ===========================================================================
__global__ __launch_bounds__(256) void gemm_tf32x3(
    const float* __restrict__ emb, const float* __restrict__ cw) {
    __shared__ uint32_t Ah[BM * LDSS], Al[BM * LDSS];
    __shared__ uint32_t Bh[BN * LDSS], Bl[BN * LDSS];

    const int tid = threadIdx.x;
    const int wid = tid >> 5, lid = tid & 31;
    const int qid = lid >> 2, qlane = lid & 3;
    const int m0 = blockIdx.y * BM, n0 = blockIdx.x * BN;
    const int wm = (wid >> 2) * 64;
    const int wn = (wid & 3) * 32;

    float acc[4][4][4];
#pragma unroll
    for (int mt = 0; mt < 4; mt++)
#pragma unroll
        for (int nt = 0; nt < 4; nt++)
#pragma unroll
            for (int j = 0; j < 4; j++) acc[mt][nt][j] = 0.f;

    // per-thread global load mapping: 2 float4 for A, 2 for B
    const int row_ld = tid >> 2;       // it=0 row (0..63); it=1 adds 64
    const int c4_ld  = tid & 3;
    const float4 z4 = make_float4(0.f, 0.f, 0.f, 0.f);

    float4 avA[2], avB[2];

    // ---- prefetch chunk 0 ----
#pragma unroll
    for (int it = 0; it < 2; it++) {
        int row = row_ld + it * 64;
        int gk4 = c4_ld;               // chunk 0: float4 cols 0..3
        int gm = m0 + row, gn = n0 + row;
        avA[it] = (gm < M_V) ? *(const float4*)(emb + (size_t)gm * K_D + gk4 * 4) : z4;
        avB[it] = (gn < N_F) ? *(const float4*)(cw + (size_t)gn * K_D + gk4 * 4) : z4;
    }

    for (int c = 0; c < NCHUNK; c++) {
        __syncthreads();   // previous chunk's compute done before overwrite
        // ---- split + store to smem ----
#pragma unroll
        for (int it = 0; it < 2; it++) {
            int row = row_ld + it * 64;
            int off = row * LDSS + c4_ld * 4;
            float xs[4] = {avA[it].x, avA[it].y, avA[it].z, avA[it].w};
            uint4 h4, l4;
            {
                uint32_t h0 = f2tf32(xs[0]), h1 = f2tf32(xs[1]),
                         h2 = f2tf32(xs[2]), h3 = f2tf32(xs[3]);
                h4 = make_uint4(h0, h1, h2, h3);
                l4 = make_uint4(f2tf32(xs[0] - __uint_as_float(h0)),
                                f2tf32(xs[1] - __uint_as_float(h1)),
                                f2tf32(xs[2] - __uint_as_float(h2)),
                                f2tf32(xs[3] - __uint_as_float(h3)));
            }
            *(uint4*)(Ah + off) = h4;
            *(uint4*)(Al + off) = l4;
            float ys[4] = {avB[it].x, avB[it].y, avB[it].z, avB[it].w};
            {
                uint32_t h0 = f2tf32(ys[0]), h1 = f2tf32(ys[1]),
                         h2 = f2tf32(ys[2]), h3 = f2tf32(ys[3]);
                h4 = make_uint4(h0, h1, h2, h3);
                l4 = make_uint4(f2tf32(ys[0] - __uint_as_float(h0)),
                                f2tf32(ys[1] - __uint_as_float(h1)),
                                f2tf32(ys[2] - __uint_as_float(h2)),
                                f2tf32(ys[3] - __uint_as_float(h3)));
            }
            *(uint4*)(Bh + off) = h4;
            *(uint4*)(Bl + off) = l4;
        }
        __syncthreads();

        // ---- prefetch next chunk ----
        if (c + 1 < NCHUNK) {
#pragma unroll
            for (int it = 0; it < 2; it++) {
                int row = row_ld + it * 64;
                int gk4 = (c + 1) * 4 + c4_ld;
                bool kok = gk4 < 75;           // K_D/4 = 75 valid float4 cols
                int gm = m0 + row, gn = n0 + row;
                avA[it] = (kok && gm < M_V)
                              ? *(const float4*)(emb + (size_t)gm * K_D + gk4 * 4) : z4;
                avB[it] = (kok && gn < N_F)
                              ? *(const float4*)(cw + (size_t)gn * K_D + gk4 * 4) : z4;
            }
        }

        // ---- compute: 2 k8 steps ----
#pragma unroll
        for (int kk = 0; kk < 16; kk += 8) {
            uint32_t bh[4][2], bl[4][2];
#pragma unroll
            for (int nt = 0; nt < 4; nt++) {
                int nb = (wn + nt * 8 + qid) * LDSS + kk + qlane;
                bh[nt][0] = Bh[nb];     bh[nt][1] = Bh[nb + 4];
                bl[nt][0] = Bl[nb];     bl[nt][1] = Bl[nb + 4];
            }
#pragma unroll
            for (int mt = 0; mt < 4; mt++) {
                int r0 = (wm + mt * 16 + qid) * LDSS + kk + qlane;
                int r1 = r0 + 8 * LDSS;
                uint32_t ah[4] = {Ah[r0], Ah[r1], Ah[r0 + 4], Ah[r1 + 4]};
                uint32_t al[4] = {Al[r0], Al[r1], Al[r0 + 4], Al[r1 + 4]};
#pragma unroll
                for (int nt = 0; nt < 4; nt++) {
                    mma8(acc[mt][nt], ah, bh[nt]);   // hi*hi
                    mma8(acc[mt][nt], ah, bl[nt]);   // hi*lo
                    mma8(acc[mt][nt], al, bh[nt]);   // lo*hi
                }
            }
        }
    }

    // ---- epilogue ----
#pragma unroll
    for (int mt = 0; mt < 4; mt++) {
        int mlo = m0 + wm + mt * 16 + qid;
        int mhi = mlo + 8;
#pragma unroll
        for (int nt = 0; nt < 4; nt++) {
            int n = n0 + wn + nt * 8 + qlane * 2;
            if (n < N_F) {
                if (mlo < M_V)
                    *(float2*)(g_S + (size_t)mlo * N_F + n) =
                        make_float2(acc[mt][nt][0], acc[mt][nt][1]);
                if (mhi < M_V)
                    *(float2*)(g_S + (size_t)mhi * N_F + n) =
                        make_float2(acc[mt][nt][2], acc[mt][nt][3]);
            }
        }
    }
}

// ===========================================================================
// Phase 2: per (b,f): first-index argmax over t of S[inp[b,t],f];
// val = relu(max + conv_b[f]); contrib = val*(fc_w[1,f]-fc_w[0,f]);
// token[b,argmax] += contrib; token += fc_b[1]-fc_b[0]. Deterministic.
// ===========================================================================
__global__ __launch_bounds__(1024) void reduce_scatter(
    const int* __restrict__ inp, const float* __restrict__ cb,
    const float* __restrict__ fcw, const float* __restrict__ fcb,
    float* __restrict__ out) {
    __shared__ int   sw[L_L];
    __shared__ int   sbt[N_F];
    __shared__ float sct[N_F];

    const int b = blockIdx.x;
    const int tid = threadIdx.x;

    if (tid < L_L) sw[tid] = inp[b * L_L + tid];
    __syncthreads();

    const int f = tid;
    if (f < N_F) {
        const float* Sf = g_S + f;
        float best = -3.4e38f;
        int bestt = 0;
        for (int t0 = 0; t0 < L_L; t0 += 8) {
            float vv[8];
#pragma unroll
            for (int j = 0; j < 8; j++)
                vv[j] = Sf[(size_t)sw[t0 + j] * N_F];
#pragma unroll
            for (int j = 0; j < 8; j++) {
                if (vv[j] > best) { best = vv[j]; bestt = t0 + j; }  // strict > => first idx
            }
        }
        float val = fmaxf(best + cb[f], 0.f);          // relu(max) == max(relu)
        float contrib = val * (fcw[N_F + f] - fcw[f]); // zero when val==0 -> index moot
        sbt[f] = bestt;
        sct[f] = contrib;
    }
    __syncthreads();

    if (tid < L_L) {
        float accv = fcb[1] - fcb[0];
        for (int ff = 0; ff < N_F; ff++) {
            if (sbt[ff] == tid) accv += sct[ff];
        }
        out[b * L_L + tid] = accv;
    }
}

extern "C" void kernel_launch(void* const* d_in, const int* in_sizes, int n_in,
                              void* d_out, int out_size) {
    const int*   inp    = (const int*)d_in[0];
    const float* emb    = (const float*)d_in[1];
    const float* conv_w = (const float*)d_in[2];   // [1000,1,300] contiguous
    const float* conv_b = (const float*)d_in[3];
    const float* fc_w   = (const float*)d_in[4];   // [2,1000]
    const float* fc_b   = (const float*)d_in[5];
    float* out = (float*)d_out;

    dim3 g1(8, 391);   // n-tiles x m-tiles
    gemm_tf32x3<<<g1, 256>>>(emb, conv_w);
    reduce_scatter<<<B_B, 1024>>>(inp, conv_b, fc_w, fc_b, out);
}